// round 10
// baseline (speedup 1.0000x reference)
#include <cuda_runtime.h>

#define N_NODES 50000
#define N_EDGES 800000
#define IN_FEAT 512
#define OUT_FEAT 128

// Scratch (no allocs allowed): intermediate x = feat @ W.
__device__ float g_x[(size_t)N_NODES * OUT_FEAT];   // 25.6 MB

// ---------------------------------------------------------------------------
// 3xTF32 helpers
// ---------------------------------------------------------------------------
__device__ __forceinline__ void split_tf32(float a, unsigned& hi, unsigned& lo) {
    unsigned h;
    asm("cvt.rna.tf32.f32 %0, %1;" : "=r"(h) : "f"(a));
    float l = a - __uint_as_float(h);   // exact (Dekker split)
    unsigned lw;
    asm("cvt.rna.tf32.f32 %0, %1;" : "=r"(lw) : "f"(l));
    hi = h; lo = lw;
}

__device__ __forceinline__ void mma_tf32(float* d, const unsigned* a, const unsigned* b) {
    asm volatile(
        "mma.sync.aligned.m16n8k8.row.col.f32.tf32.tf32.f32 "
        "{%0,%1,%2,%3}, {%4,%5,%6,%7}, {%8,%9}, {%0,%1,%2,%3};"
        : "+f"(d[0]), "+f"(d[1]), "+f"(d[2]), "+f"(d[3])
        : "r"(a[0]), "r"(a[1]), "r"(a[2]), "r"(a[3]), "r"(b[0]), "r"(b[1]));
}

// cp.async 16B with zero-fill predication (src_bytes = 16 or 0).
__device__ __forceinline__ void cp_async16(void* smem_dst, const void* gsrc, int src_bytes) {
    unsigned saddr = (unsigned)__cvta_generic_to_shared(smem_dst);
    asm volatile("cp.async.cg.shared.global [%0], [%1], 16, %2;"
                 :: "r"(saddr), "l"(gsrc), "r"(src_bytes));
}
__device__ __forceinline__ void cp_commit() {
    asm volatile("cp.async.commit_group;");
}
template <int N>
__device__ __forceinline__ void cp_wait() {
    asm volatile("cp.async.wait_group %0;" :: "n"(N));
}

// ---------------------------------------------------------------------------
// Kernel 1: 3xTF32 tensor-core GEMM  C[M,128] = A[M,512] * B[512,128]
// CTA tile 64x128, BK=16, 256 threads = 8 warps (2 in M x 4 in N),
// warp tile 32x32. 3 CTAs/SM. Double-buffered cp.async pipeline.
// Conflict-free smem layouts for the m16n8k8 fragment pattern:
//   A: [m][k] stride 20  (bank = (20*gid + tig) % 32 -> 32 distinct)
//   B: [k][n] stride 136 (bank = (8*tig + 8*nt + gid) % 32 -> distinct)
// ---------------------------------------------------------------------------
#define BM 64
#define BK 16
#define NKB (IN_FEAT / BK)    // 32
#define A_STRIDE 20
#define B_STRIDE 136

__global__ __launch_bounds__(256, 3) void gemm_kernel(const float* __restrict__ A,
                                                      const float* __restrict__ B,
                                                      int M) {
    __shared__ float As[2][BM * A_STRIDE];    // 2 x 5120 B
    __shared__ float Bs[2][BK * B_STRIDE];    // 2 x 8704 B

    const int tid  = threadIdx.x;
    const int wid  = tid >> 5;
    const int lane = tid & 31;
    const int gid  = lane >> 2;     // 0..7
    const int tig  = lane & 3;      // 0..3
    const int wm   = wid >> 2;      // 0..1 (M direction)
    const int wn   = wid & 3;       // 0..3 (N direction)
    const int block_row = blockIdx.x * BM;

    // Staging coordinates. A tile: 64 rows x 16 k = 256 float4, 1/thread.
    const int sa_m  = tid >> 2;         // 0..63
    const int sa_c4 = tid & 3;          // float4 index within the 16-wide row
    // B tile: 16 rows x 128 n = 512 float4, 2/thread (adjacent pair).
    const int sb_r = tid >> 4;          // 0..15 (k)
    const int sb_c = tid & 15;          // 0..15 -> n offset *8

    const int a_row    = block_row + sa_m;
    const int a_valid  = (a_row < M) ? 16 : 0;
    const int a_row_cl = (a_row < M) ? a_row : (M - 1);
    const float* a_base = A + (size_t)a_row_cl * IN_FEAT + sa_c4 * 4;
    float* a_dst0 = &As[0][sa_m * A_STRIDE + sa_c4 * 4];
    float* a_dst1 = &As[1][sa_m * A_STRIDE + sa_c4 * 4];
    const float* b_base = B + (size_t)sb_r * OUT_FEAT + sb_c * 8;
    float* b_dst0 = &Bs[0][sb_r * B_STRIDE + sb_c * 8];
    float* b_dst1 = &Bs[1][sb_r * B_STRIDE + sb_c * 8];

    float acc[2][4][4];
#pragma unroll
    for (int mt = 0; mt < 2; mt++)
#pragma unroll
        for (int nt = 0; nt < 4; nt++)
#pragma unroll
            for (int r = 0; r < 4; r++) acc[mt][nt][r] = 0.0f;

    // Prologue: stage k-block 0 into buffer 0
    cp_async16(a_dst0,     a_base,     a_valid);
    cp_async16(b_dst0,     b_base,     16);
    cp_async16(b_dst0 + 4, b_base + 4, 16);
    cp_commit();

    for (int kb = 0; kb < NKB; kb++) {
        const int buf = kb & 1;

        if (kb + 1 < NKB) {
            const float* an = a_base + (kb + 1) * BK;
            const float* bn = b_base + (size_t)(kb + 1) * BK * OUT_FEAT;
            float* ad = buf ? a_dst0 : a_dst1;
            float* bd = buf ? b_dst0 : b_dst1;
            cp_async16(ad,     an,     a_valid);
            cp_async16(bd,     bn,     16);
            cp_async16(bd + 4, bn + 4, 16);
            cp_commit();
            cp_wait<1>();
        } else {
            cp_wait<0>();
        }
        __syncthreads();

        const float* __restrict__ Ab = As[buf];
        const float* __restrict__ Bb = Bs[buf];

#pragma unroll
        for (int ks = 0; ks < 2; ks++) {
            const int kk = ks * 8;
            unsigned ah[2][4], al[2][4];
#pragma unroll
            for (int mt = 0; mt < 2; mt++) {
                int m0 = (wm * 32 + mt * 16 + gid) * A_STRIDE;
                int m1 = m0 + 8 * A_STRIDE;
                float a0 = Ab[m0 + kk + tig];
                float a1 = Ab[m1 + kk + tig];
                float a2 = Ab[m0 + kk + tig + 4];
                float a3 = Ab[m1 + kk + tig + 4];
                split_tf32(a0, ah[mt][0], al[mt][0]);
                split_tf32(a1, ah[mt][1], al[mt][1]);
                split_tf32(a2, ah[mt][2], al[mt][2]);
                split_tf32(a3, ah[mt][3], al[mt][3]);
            }
#pragma unroll
            for (int nt = 0; nt < 4; nt++) {
                int nc = wn * 32 + nt * 8 + gid;
                float b0 = Bb[(kk + tig) * B_STRIDE + nc];
                float b1 = Bb[(kk + tig + 4) * B_STRIDE + nc];
                unsigned bh[2], bl[2];
                split_tf32(b0, bh[0], bl[0]);
                split_tf32(b1, bh[1], bl[1]);
#pragma unroll
                for (int mt = 0; mt < 2; mt++) {
                    mma_tf32(acc[mt][nt], ah[mt], bl);   // hi x lo
                    mma_tf32(acc[mt][nt], al[mt], bh);   // lo x hi
                    mma_tf32(acc[mt][nt], ah[mt], bh);   // hi x hi
                }
            }
        }
        __syncthreads();
    }

    // ---- Epilogue: fragment c0,c1 at (gid, 2tig..+1); c2,c3 at (gid+8, ..) ----
#pragma unroll
    for (int mt = 0; mt < 2; mt++) {
#pragma unroll
        for (int nt = 0; nt < 4; nt++) {
            int row0 = block_row + wm * 32 + mt * 16 + gid;
            int col  = wn * 32 + nt * 8 + 2 * tig;
            if (row0 < M) {
                float2 v = make_float2(acc[mt][nt][0], acc[mt][nt][1]);
                *(float2*)(g_x + (size_t)row0 * OUT_FEAT + col) = v;
            }
            int row1 = row0 + 8;
            if (row1 < M) {
                float2 v = make_float2(acc[mt][nt][2], acc[mt][nt][3]);
                *(float2*)(g_x + (size_t)row1 * OUT_FEAT + col) = v;
            }
        }
    }
}

// ---------------------------------------------------------------------------
// Kernel 2: SpMM + multispike, with fused CSR range discovery.
// One warp per output row. Row range found by in-warp binary search over the
// sorted rows[] (even lanes search lower_bound(gw), odd lanes gw+1; top tree
// levels are L1/L2-hot across warps). Each lane owns a float4 (4 features);
// gathers hit L2 (x table is 25.6 MB, fits 126 MB L2).
// ---------------------------------------------------------------------------
__device__ __forceinline__ float multispike(float x) {
    return floorf(fminf(fmaxf(4.0f * x, 0.0f), 4.0f) + 0.5f) * 0.25f;
}

__global__ __launch_bounds__(256) void spmm_kernel(const int* __restrict__ rows,
                                                   const int* __restrict__ cols,
                                                   const float* __restrict__ ew,
                                                   float* __restrict__ out) {
    int gw   = (blockIdx.x * blockDim.x + threadIdx.x) >> 5;  // global warp = row
    int lane = threadIdx.x & 31;
    if (gw >= N_NODES) return;

    // lower_bound(rows, gw + (lane&1)); all even lanes redundant (broadcast loads).
    int target = gw + (lane & 1);
    int lo = 0, hi = N_EDGES;
    while (lo < hi) {
        int mid = (lo + hi) >> 1;
        if (__ldg(rows + mid) < target) lo = mid + 1; else hi = mid;
    }
    int s = __shfl_sync(0xffffffffu, lo, 0);
    int e = __shfl_sync(0xffffffffu, lo, 1);

    const float4* __restrict__ xb = (const float4*)g_x;  // 32 float4 per row

    float ax = 0.f, ay = 0.f, az = 0.f, aw = 0.f;
    int i = s;
    for (; i + 1 < e; i += 2) {
        int   c0 = __ldg(cols + i);
        int   c1 = __ldg(cols + i + 1);
        float w0 = __ldg(ew + i);
        float w1 = __ldg(ew + i + 1);
        float4 v0 = __ldg(xb + (size_t)c0 * 32 + lane);
        float4 v1 = __ldg(xb + (size_t)c1 * 32 + lane);
        ax += w0 * v0.x; ay += w0 * v0.y; az += w0 * v0.z; aw += w0 * v0.w;
        ax += w1 * v1.x; ay += w1 * v1.y; az += w1 * v1.z; aw += w1 * v1.w;
    }
    if (i < e) {
        int   c0 = __ldg(cols + i);
        float w0 = __ldg(ew + i);
        float4 v0 = __ldg(xb + (size_t)c0 * 32 + lane);
        ax += w0 * v0.x; ay += w0 * v0.y; az += w0 * v0.z; aw += w0 * v0.w;
    }

    float4 r;
    r.x = multispike(ax);
    r.y = multispike(ay);
    r.z = multispike(az);
    r.w = multispike(aw);
    ((float4*)out)[(size_t)gw * 32 + lane] = r;
}

// ---------------------------------------------------------------------------
// Launch
// ---------------------------------------------------------------------------
extern "C" void kernel_launch(void* const* d_in, const int* in_sizes, int n_in,
                              void* d_out, int out_size) {
    const float* feat   = (const float*)d_in[0];   // [50000, 512]
    const float* weight = (const float*)d_in[1];   // [512, 128]
    const int*   rows   = (const int*)  d_in[2];   // [800000] sorted
    const int*   cols   = (const int*)  d_in[3];   // [800000]
    const float* ew     = (const float*)d_in[4];   // [800000]
    float* out = (float*)d_out;                    // [50000, 128]

    // 1) GEMM into scratch (3xTF32 tensor cores, 64x128 tiles, cp.async)
    int gemm_blocks = (N_NODES + BM - 1) / BM;     // 782
    gemm_kernel<<<gemm_blocks, 256>>>(feat, weight, N_NODES);

    // 2) SpMM + activation (fused row-range binary search): one warp per row
    int spmm_blocks = (N_NODES * 32 + 255) / 256;  // 6250
    spmm_kernel<<<spmm_blocks, 256>>>(rows, cols, ew, out);
}

// round 13
// speedup vs baseline: 1.0328x; 1.0328x over previous
#include <cuda_runtime.h>

#define N_NODES 50000
#define N_EDGES 800000
#define IN_FEAT 512
#define OUT_FEAT 128

// Scratch (no allocs allowed): intermediate x = feat @ W, CSR row pointers.
__device__ float g_x[(size_t)N_NODES * OUT_FEAT];   // 25.6 MB
__device__ int   g_row_ptr[N_NODES + 1];

// ---------------------------------------------------------------------------
// 3xTF32 helpers
// ---------------------------------------------------------------------------
__device__ __forceinline__ void split_tf32(float a, unsigned& hi, unsigned& lo) {
    unsigned h;
    asm("cvt.rna.tf32.f32 %0, %1;" : "=r"(h) : "f"(a));
    float l = a - __uint_as_float(h);   // exact (Dekker split)
    unsigned lw;
    asm("cvt.rna.tf32.f32 %0, %1;" : "=r"(lw) : "f"(l));
    hi = h; lo = lw;
}

__device__ __forceinline__ void mma_tf32(float* d, const unsigned* a, const unsigned* b) {
    asm volatile(
        "mma.sync.aligned.m16n8k8.row.col.f32.tf32.tf32.f32 "
        "{%0,%1,%2,%3}, {%4,%5,%6,%7}, {%8,%9}, {%0,%1,%2,%3};"
        : "+f"(d[0]), "+f"(d[1]), "+f"(d[2]), "+f"(d[3])
        : "r"(a[0]), "r"(a[1]), "r"(a[2]), "r"(a[3]), "r"(b[0]), "r"(b[1]));
}

// cp.async 16B with zero-fill predication (src_bytes = 16 or 0).
__device__ __forceinline__ void cp_async16(void* smem_dst, const void* gsrc, int src_bytes) {
    unsigned saddr = (unsigned)__cvta_generic_to_shared(smem_dst);
    asm volatile("cp.async.cg.shared.global [%0], [%1], 16, %2;"
                 :: "r"(saddr), "l"(gsrc), "r"(src_bytes));
}
__device__ __forceinline__ void cp_commit() {
    asm volatile("cp.async.commit_group;");
}
template <int N>
__device__ __forceinline__ void cp_wait() {
    asm volatile("cp.async.wait_group %0;" :: "n"(N));
}

// ---------------------------------------------------------------------------
// Kernel 1: 3xTF32 tensor-core GEMM  C[M,128] = A[M,512] * B[512,128]
// CTA tile 128x128, BK=32 (halved barrier count vs BK=16), 256 threads =
// 8 warps (4 in M x 2 in N), warp tile 32x64. 2 CTAs/SM, double-buffered
// cp.async. CTAs 0..195 also build g_row_ptr (binary search) overlapped
// with the staged prologue loads — removes a serialized 12us launch.
// Conflict-free smem layouts for the m16n8k8 fragment pattern:
//   A: [m][k] stride 36  (bank = (4*gid + tig) % 32 -> 32 distinct)
//   B: [k][n] stride 136 (bank = (8*tig + 8*nt + gid) % 32 -> distinct)
// ---------------------------------------------------------------------------
#define BM 128
#define BK 32
#define NKB (IN_FEAT / BK)    // 16
#define A_STRIDE 36
#define B_STRIDE 136

__global__ __launch_bounds__(256, 2) void gemm_kernel(const float* __restrict__ A,
                                                      const float* __restrict__ B,
                                                      const int* __restrict__ rows,
                                                      int M) {
    __shared__ float As[2][BM * A_STRIDE];    // 2 x 18432 B
    __shared__ float Bs[2][BK * B_STRIDE];    // 2 x 17408 B

    const int tid  = threadIdx.x;
    const int wid  = tid >> 5;
    const int lane = tid & 31;
    const int gid  = lane >> 2;     // 0..7
    const int tig  = lane & 3;      // 0..3
    const int wm   = wid >> 1;      // 0..3 (M direction)
    const int wn   = wid & 1;       // 0..1 (N direction)
    const int block_row = blockIdx.x * BM;

    // Staging coordinates.
    // A tile: 128 rows x 32 k = 1024 float4, 4/thread (one 16-float run).
    const int sa_m    = tid >> 1;       // 0..127
    const int sa_half = tid & 1;        // k offset 0/16
    // B tile: 32 rows x 128 n = 1024 float4, 4/thread (one 16-float run).
    const int sb_r = tid >> 3;          // 0..31 (k)
    const int sb_c = tid & 7;           // n offset *16

    const int a_row    = block_row + sa_m;
    const int a_valid  = (a_row < M) ? 16 : 0;
    const int a_row_cl = (a_row < M) ? a_row : (M - 1);
    const float* a_base = A + (size_t)a_row_cl * IN_FEAT + sa_half * 16;
    float* a_dst0 = &As[0][sa_m * A_STRIDE + sa_half * 16];
    float* a_dst1 = &As[1][sa_m * A_STRIDE + sa_half * 16];
    const float* b_base = B + (size_t)sb_r * OUT_FEAT + sb_c * 16;
    float* b_dst0 = &Bs[0][sb_r * B_STRIDE + sb_c * 16];
    float* b_dst1 = &Bs[1][sb_r * B_STRIDE + sb_c * 16];

    float acc[2][8][4];
#pragma unroll
    for (int mt = 0; mt < 2; mt++)
#pragma unroll
        for (int nt = 0; nt < 8; nt++)
#pragma unroll
            for (int r = 0; r < 4; r++) acc[mt][nt][r] = 0.0f;

    // Prologue: stage k-block 0 into buffer 0
#pragma unroll
    for (int q = 0; q < 4; q++) {
        cp_async16(a_dst0 + 4 * q, a_base + 4 * q, a_valid);
        cp_async16(b_dst0 + 4 * q, b_base + 4 * q, 16);
    }
    cp_commit();

    // Overlapped side job: CTAs 0..195 build g_row_ptr (50176 threads cover
    // 50001 entries). Latency-bound LDG chain hidden under staged cp.async.
    if (blockIdx.x < 196) {
        int node = blockIdx.x * 256 + tid;
        if (node <= N_NODES) {
            int lo = 0, hi = N_EDGES;
            while (lo < hi) {
                int mid = (lo + hi) >> 1;
                if (__ldg(rows + mid) < node) lo = mid + 1; else hi = mid;
            }
            g_row_ptr[node] = lo;
        }
    }

    for (int kb = 0; kb < NKB; kb++) {
        const int buf = kb & 1;

        if (kb + 1 < NKB) {
            const float* an = a_base + (kb + 1) * BK;
            const float* bn = b_base + (size_t)(kb + 1) * BK * OUT_FEAT;
            float* ad = buf ? a_dst0 : a_dst1;
            float* bd = buf ? b_dst0 : b_dst1;
#pragma unroll
            for (int q = 0; q < 4; q++) {
                cp_async16(ad + 4 * q, an + 4 * q, a_valid);
                cp_async16(bd + 4 * q, bn + 4 * q, 16);
            }
            cp_commit();
            cp_wait<1>();
        } else {
            cp_wait<0>();
        }
        __syncthreads();

        const float* __restrict__ Ab = As[buf];
        const float* __restrict__ Bb = Bs[buf];

#pragma unroll
        for (int ks = 0; ks < 4; ks++) {
            const int kk = ks * 8;
            unsigned ah[2][4], al[2][4];
#pragma unroll
            for (int mt = 0; mt < 2; mt++) {
                int m0 = (wm * 32 + mt * 16 + gid) * A_STRIDE;
                int m1 = m0 + 8 * A_STRIDE;
                float a0 = Ab[m0 + kk + tig];
                float a1 = Ab[m1 + kk + tig];
                float a2 = Ab[m0 + kk + tig + 4];
                float a3 = Ab[m1 + kk + tig + 4];
                split_tf32(a0, ah[mt][0], al[mt][0]);
                split_tf32(a1, ah[mt][1], al[mt][1]);
                split_tf32(a2, ah[mt][2], al[mt][2]);
                split_tf32(a3, ah[mt][3], al[mt][3]);
            }
#pragma unroll
            for (int nt = 0; nt < 8; nt++) {
                int nc = wn * 64 + nt * 8 + gid;
                float b0 = Bb[(kk + tig) * B_STRIDE + nc];
                float b1 = Bb[(kk + tig + 4) * B_STRIDE + nc];
                unsigned bh[2], bl[2];
                split_tf32(b0, bh[0], bl[0]);
                split_tf32(b1, bh[1], bl[1]);
#pragma unroll
                for (int mt = 0; mt < 2; mt++) {
                    mma_tf32(acc[mt][nt], ah[mt], bl);   // hi x lo
                    mma_tf32(acc[mt][nt], al[mt], bh);   // lo x hi
                    mma_tf32(acc[mt][nt], ah[mt], bh);   // hi x hi
                }
            }
        }
        __syncthreads();
    }

    // ---- Epilogue: fragment c0,c1 at (gid, 2tig..+1); c2,c3 at (gid+8, ..) ----
#pragma unroll
    for (int mt = 0; mt < 2; mt++) {
#pragma unroll
        for (int nt = 0; nt < 8; nt++) {
            int row0 = block_row + wm * 32 + mt * 16 + gid;
            int col  = wn * 64 + nt * 8 + 2 * tig;
            if (row0 < M) {
                float2 v = make_float2(acc[mt][nt][0], acc[mt][nt][1]);
                *(float2*)(g_x + (size_t)row0 * OUT_FEAT + col) = v;
            }
            int row1 = row0 + 8;
            if (row1 < M) {
                float2 v = make_float2(acc[mt][nt][2], acc[mt][nt][3]);
                *(float2*)(g_x + (size_t)row1 * OUT_FEAT + col) = v;
            }
        }
    }
}

// ---------------------------------------------------------------------------
// Kernel 2: SpMM + multispike. One warp per output row; each lane owns a
// float4 (4 features). Gathers hit L2 (x table is 25.6 MB, fits 126 MB L2).
// Row ranges come from g_row_ptr built inside the GEMM kernel.
// ---------------------------------------------------------------------------
__device__ __forceinline__ float multispike(float x) {
    return floorf(fminf(fmaxf(4.0f * x, 0.0f), 4.0f) + 0.5f) * 0.25f;
}

__global__ __launch_bounds__(256) void spmm_kernel(const int* __restrict__ cols,
                                                   const float* __restrict__ ew,
                                                   float* __restrict__ out) {
    int gw   = (blockIdx.x * blockDim.x + threadIdx.x) >> 5;  // global warp = row
    int lane = threadIdx.x & 31;
    if (gw >= N_NODES) return;

    int s = g_row_ptr[gw];
    int e = g_row_ptr[gw + 1];

    const float4* __restrict__ xb = (const float4*)g_x;  // 32 float4 per row

    float ax = 0.f, ay = 0.f, az = 0.f, aw = 0.f;
    int i = s;
    for (; i + 1 < e; i += 2) {
        int   c0 = __ldg(cols + i);
        int   c1 = __ldg(cols + i + 1);
        float w0 = __ldg(ew + i);
        float w1 = __ldg(ew + i + 1);
        float4 v0 = __ldg(xb + (size_t)c0 * 32 + lane);
        float4 v1 = __ldg(xb + (size_t)c1 * 32 + lane);
        ax += w0 * v0.x; ay += w0 * v0.y; az += w0 * v0.z; aw += w0 * v0.w;
        ax += w1 * v1.x; ay += w1 * v1.y; az += w1 * v1.z; aw += w1 * v1.w;
    }
    if (i < e) {
        int   c0 = __ldg(cols + i);
        float w0 = __ldg(ew + i);
        float4 v0 = __ldg(xb + (size_t)c0 * 32 + lane);
        ax += w0 * v0.x; ay += w0 * v0.y; az += w0 * v0.z; aw += w0 * v0.w;
    }

    float4 r;
    r.x = multispike(ax);
    r.y = multispike(ay);
    r.z = multispike(az);
    r.w = multispike(aw);
    ((float4*)out)[(size_t)gw * 32 + lane] = r;
}

// ---------------------------------------------------------------------------
// Launch
// ---------------------------------------------------------------------------
extern "C" void kernel_launch(void* const* d_in, const int* in_sizes, int n_in,
                              void* d_out, int out_size) {
    const float* feat   = (const float*)d_in[0];   // [50000, 512]
    const float* weight = (const float*)d_in[1];   // [512, 128]
    const int*   rows   = (const int*)  d_in[2];   // [800000] sorted
    const int*   cols   = (const int*)  d_in[3];   // [800000]
    const float* ew     = (const float*)d_in[4];   // [800000]
    float* out = (float*)d_out;                    // [50000, 128]

    // 1) GEMM into scratch (3xTF32, BK=32, cp.async) + fused rowptr build
    int gemm_blocks = (N_NODES + BM - 1) / BM;     // 391
    gemm_kernel<<<gemm_blocks, 256>>>(feat, weight, rows, N_NODES);

    // 2) SpMM + activation: one warp per row
    int spmm_blocks = (N_NODES * 32 + 255) / 256;  // 6250
    spmm_kernel<<<spmm_blocks, 256>>>(cols, ew, out);
}

// round 16
// speedup vs baseline: 1.1137x; 1.0783x over previous
#include <cuda_runtime.h>

#define N_NODES 50000
#define N_EDGES 800000
#define IN_FEAT 512
#define OUT_FEAT 128

// Scratch (no allocs allowed): intermediate x = feat @ W, CSR row pointers.
__device__ float g_x[(size_t)N_NODES * OUT_FEAT];   // 25.6 MB
__device__ int   g_row_ptr[N_NODES + 1];

// ---------------------------------------------------------------------------
// 3xTF32 helpers
// ---------------------------------------------------------------------------
__device__ __forceinline__ void split_tf32(float a, unsigned& hi, unsigned& lo) {
    unsigned h;
    asm("cvt.rna.tf32.f32 %0, %1;" : "=r"(h) : "f"(a));
    float l = a - __uint_as_float(h);   // exact (Dekker split)
    unsigned lw;
    asm("cvt.rna.tf32.f32 %0, %1;" : "=r"(lw) : "f"(l));
    hi = h; lo = lw;
}

__device__ __forceinline__ void mma_tf32(float* d, const unsigned* a, const unsigned* b) {
    asm volatile(
        "mma.sync.aligned.m16n8k8.row.col.f32.tf32.tf32.f32 "
        "{%0,%1,%2,%3}, {%4,%5,%6,%7}, {%8,%9}, {%0,%1,%2,%3};"
        : "+f"(d[0]), "+f"(d[1]), "+f"(d[2]), "+f"(d[3])
        : "r"(a[0]), "r"(a[1]), "r"(a[2]), "r"(a[3]), "r"(b[0]), "r"(b[1]));
}

// cp.async 16B with zero-fill predication (src_bytes = 16 or 0).
__device__ __forceinline__ void cp_async16(void* smem_dst, const void* gsrc, int src_bytes) {
    unsigned saddr = (unsigned)__cvta_generic_to_shared(smem_dst);
    asm volatile("cp.async.cg.shared.global [%0], [%1], 16, %2;"
                 :: "r"(saddr), "l"(gsrc), "r"(src_bytes));
}
__device__ __forceinline__ void cp_commit() {
    asm volatile("cp.async.commit_group;");
}
template <int N>
__device__ __forceinline__ void cp_wait() {
    asm volatile("cp.async.wait_group %0;" :: "n"(N));
}

// ---------------------------------------------------------------------------
// Kernel 1: 3xTF32 tensor-core GEMM  C[M,128] = A[M,512] * B[512,128]
// CTA tile 128x128, BK=16 (R9 measured-best shape), 256 threads = 8 warps
// (4 in M x 2 in N), warp tile 32x64. 2 CTAs/SM. THREE-stage cp.async ring
// (prefetch distance 2) for a full extra stage of latency budget.
// CTAs 0..195 also build g_row_ptr overlapped with the prologue.
// Conflict-free smem layouts for the m16n8k8 fragment pattern:
//   A: [m][k] stride 20  (bank = (20*gid + tig) % 32 -> 32 distinct)
//   B: [k][n] stride 136 (bank = (8*tig + 8*nt + gid) % 32 -> distinct)
// ---------------------------------------------------------------------------
#define BM 128
#define BK 16
#define NKB (IN_FEAT / BK)    // 32
#define NSTAGE 3
#define A_STRIDE 20
#define B_STRIDE 136

__global__ __launch_bounds__(256, 2) void gemm_kernel(const float* __restrict__ A,
                                                      const float* __restrict__ B,
                                                      const int* __restrict__ rows,
                                                      int M) {
    __shared__ float As[NSTAGE][BM * A_STRIDE];   // 3 x 10240 B
    __shared__ float Bs[NSTAGE][BK * B_STRIDE];   // 3 x  8704 B

    const int tid  = threadIdx.x;
    const int wid  = tid >> 5;
    const int lane = tid & 31;
    const int gid  = lane >> 2;     // 0..7
    const int tig  = lane & 3;      // 0..3
    const int wm   = wid >> 1;      // 0..3 (M direction)
    const int wn   = wid & 1;       // 0..1 (N direction)
    const int block_row = blockIdx.x * BM;

    // Staging coordinates (R9 shape).
    const int sa_m    = tid >> 1;       // 0..127
    const int sa_half = tid & 1;        // k offset 0/8
    const int sb_r    = tid >> 4;       // 0..15 (k)
    const int sb_c    = tid & 15;       // n offset *8

    const int a_row    = block_row + sa_m;
    const int a_valid  = (a_row < M) ? 16 : 0;
    const int a_row_cl = (a_row < M) ? a_row : (M - 1);
    const float* a_base = A + (size_t)a_row_cl * IN_FEAT + sa_half * 8;
    const float* b_base = B + (size_t)sb_r * OUT_FEAT + sb_c * 8;

    float* a_dst[NSTAGE];
    float* b_dst[NSTAGE];
#pragma unroll
    for (int s = 0; s < NSTAGE; s++) {
        a_dst[s] = &As[s][sa_m * A_STRIDE + sa_half * 8];
        b_dst[s] = &Bs[s][sb_r * B_STRIDE + sb_c * 8];
    }

    float acc[2][8][4];
#pragma unroll
    for (int mt = 0; mt < 2; mt++)
#pragma unroll
        for (int nt = 0; nt < 8; nt++)
#pragma unroll
            for (int r = 0; r < 4; r++) acc[mt][nt][r] = 0.0f;

    // Prologue: stage k-blocks 0 and 1.
    {
        cp_async16(a_dst[0],     a_base,     a_valid);
        cp_async16(a_dst[0] + 4, a_base + 4, a_valid);
        cp_async16(b_dst[0],     b_base,     16);
        cp_async16(b_dst[0] + 4, b_base + 4, 16);
        cp_commit();
        const float* an = a_base + BK;
        const float* bn = b_base + (size_t)BK * OUT_FEAT;
        cp_async16(a_dst[1],     an,     a_valid);
        cp_async16(a_dst[1] + 4, an + 4, a_valid);
        cp_async16(b_dst[1],     bn,     16);
        cp_async16(b_dst[1] + 4, bn + 4, 16);
        cp_commit();
    }

    // Overlapped side job: CTAs 0..195 build g_row_ptr (50176 threads cover
    // 50001 entries) under the staged prologue loads.
    if (blockIdx.x < 196) {
        int node = blockIdx.x * 256 + tid;
        if (node <= N_NODES) {
            int lo = 0, hi = N_EDGES;
            while (lo < hi) {
                int mid = (lo + hi) >> 1;
                if (__ldg(rows + mid) < node) lo = mid + 1; else hi = mid;
            }
            g_row_ptr[node] = lo;
        }
    }

    int buf = 0;           // stage being consumed this iteration
    int nxt = 2;           // ring slot for k-block kb+2
    for (int kb = 0; kb < NKB; kb++) {
        if (kb + 2 < NKB) {
            const float* an = a_base + (kb + 2) * BK;
            const float* bn = b_base + (size_t)(kb + 2) * BK * OUT_FEAT;
            cp_async16(a_dst[nxt],     an,     a_valid);
            cp_async16(a_dst[nxt] + 4, an + 4, a_valid);
            cp_async16(b_dst[nxt],     bn,     16);
            cp_async16(b_dst[nxt] + 4, bn + 4, 16);
            cp_commit();
            cp_wait<2>();
        } else if (kb + 1 < NKB) {
            cp_wait<1>();
        } else {
            cp_wait<0>();
        }
        __syncthreads();

        const float* __restrict__ Ab = As[buf];
        const float* __restrict__ Bb = Bs[buf];

#pragma unroll
        for (int ks = 0; ks < 2; ks++) {
            const int kk = ks * 8;
            unsigned ah[2][4], al[2][4];
#pragma unroll
            for (int mt = 0; mt < 2; mt++) {
                int m0 = (wm * 32 + mt * 16 + gid) * A_STRIDE;
                int m1 = m0 + 8 * A_STRIDE;
                float a0 = Ab[m0 + kk + tig];
                float a1 = Ab[m1 + kk + tig];
                float a2 = Ab[m0 + kk + tig + 4];
                float a3 = Ab[m1 + kk + tig + 4];
                split_tf32(a0, ah[mt][0], al[mt][0]);
                split_tf32(a1, ah[mt][1], al[mt][1]);
                split_tf32(a2, ah[mt][2], al[mt][2]);
                split_tf32(a3, ah[mt][3], al[mt][3]);
            }
#pragma unroll
            for (int nt = 0; nt < 8; nt++) {
                int nc = wn * 64 + nt * 8 + gid;
                float b0 = Bb[(kk + tig) * B_STRIDE + nc];
                float b1 = Bb[(kk + tig + 4) * B_STRIDE + nc];
                unsigned bh[2], bl[2];
                split_tf32(b0, bh[0], bl[0]);
                split_tf32(b1, bh[1], bl[1]);
#pragma unroll
                for (int mt = 0; mt < 2; mt++) {
                    mma_tf32(acc[mt][nt], ah[mt], bl);   // hi x lo
                    mma_tf32(acc[mt][nt], al[mt], bh);   // lo x hi
                    mma_tf32(acc[mt][nt], ah[mt], bh);   // hi x hi
                }
            }
        }
        __syncthreads();

        buf = (buf == NSTAGE - 1) ? 0 : buf + 1;
        nxt = (nxt == NSTAGE - 1) ? 0 : nxt + 1;
    }

    // ---- Epilogue: fragment c0,c1 at (gid, 2tig..+1); c2,c3 at (gid+8, ..) ----
#pragma unroll
    for (int mt = 0; mt < 2; mt++) {
#pragma unroll
        for (int nt = 0; nt < 8; nt++) {
            int row0 = block_row + wm * 32 + mt * 16 + gid;
            int col  = wn * 64 + nt * 8 + 2 * tig;
            if (row0 < M) {
                float2 v = make_float2(acc[mt][nt][0], acc[mt][nt][1]);
                *(float2*)(g_x + (size_t)row0 * OUT_FEAT + col) = v;
            }
            int row1 = row0 + 8;
            if (row1 < M) {
                float2 v = make_float2(acc[mt][nt][2], acc[mt][nt][3]);
                *(float2*)(g_x + (size_t)row1 * OUT_FEAT + col) = v;
            }
        }
    }
}

// ---------------------------------------------------------------------------
// Kernel 2: SpMM + multispike. One warp per output row; each lane owns a
// float4 (4 features). Gathers hit L2 (x table is 25.6 MB, fits 126 MB L2).
// Row ranges come from g_row_ptr built inside the GEMM kernel.
// ---------------------------------------------------------------------------
__device__ __forceinline__ float multispike(float x) {
    return floorf(fminf(fmaxf(4.0f * x, 0.0f), 4.0f) + 0.5f) * 0.25f;
}

__global__ __launch_bounds__(256) void spmm_kernel(const int* __restrict__ cols,
                                                   const float* __restrict__ ew,
                                                   float* __restrict__ out) {
    int gw   = (blockIdx.x * blockDim.x + threadIdx.x) >> 5;  // global warp = row
    int lane = threadIdx.x & 31;
    if (gw >= N_NODES) return;

    int s = g_row_ptr[gw];
    int e = g_row_ptr[gw + 1];

    const float4* __restrict__ xb = (const float4*)g_x;  // 32 float4 per row

    float ax = 0.f, ay = 0.f, az = 0.f, aw = 0.f;
    int i = s;
    for (; i + 1 < e; i += 2) {
        int   c0 = __ldg(cols + i);
        int   c1 = __ldg(cols + i + 1);
        float w0 = __ldg(ew + i);
        float w1 = __ldg(ew + i + 1);
        float4 v0 = __ldg(xb + (size_t)c0 * 32 + lane);
        float4 v1 = __ldg(xb + (size_t)c1 * 32 + lane);
        ax += w0 * v0.x; ay += w0 * v0.y; az += w0 * v0.z; aw += w0 * v0.w;
        ax += w1 * v1.x; ay += w1 * v1.y; az += w1 * v1.z; aw += w1 * v1.w;
    }
    if (i < e) {
        int   c0 = __ldg(cols + i);
        float w0 = __ldg(ew + i);
        float4 v0 = __ldg(xb + (size_t)c0 * 32 + lane);
        ax += w0 * v0.x; ay += w0 * v0.y; az += w0 * v0.z; aw += w0 * v0.w;
    }

    float4 r;
    r.x = multispike(ax);
    r.y = multispike(ay);
    r.z = multispike(az);
    r.w = multispike(aw);
    ((float4*)out)[(size_t)gw * 32 + lane] = r;
}

// ---------------------------------------------------------------------------
// Launch
// ---------------------------------------------------------------------------
extern "C" void kernel_launch(void* const* d_in, const int* in_sizes, int n_in,
                              void* d_out, int out_size) {
    const float* feat   = (const float*)d_in[0];   // [50000, 512]
    const float* weight = (const float*)d_in[1];   // [512, 128]
    const int*   rows   = (const int*)  d_in[2];   // [800000] sorted
    const int*   cols   = (const int*)  d_in[3];   // [800000]
    const float* ew     = (const float*)d_in[4];   // [800000]
    float* out = (float*)d_out;                    // [50000, 128]

    // 1) GEMM into scratch (3xTF32, BK=16, 3-stage cp.async) + fused rowptr
    int gemm_blocks = (N_NODES + BM - 1) / BM;     // 391
    gemm_kernel<<<gemm_blocks, 256>>>(feat, weight, rows, N_NODES);

    // 2) SpMM + activation: one warp per row
    int spmm_blocks = (N_NODES * 32 + 255) / 256;  // 6250
    spmm_kernel<<<spmm_blocks, 256>>>(cols, ew, out);
}